// round 14
// baseline (speedup 1.0000x reference)
#include <cuda_runtime.h>
#include <cuda_fp16.h>
#include <cstdint>

#define NOBJ 1024
#define TPB  256
#define JB   64        // actors per CTA chunk (16 chunks -> 1024 CTAs, 7 waves)
#define WST  80        // SMEM weight row stride (halfs): 160B == 32 mod 128
                       // -> conflict-free ld.shared.v2.u32 of B fragments

// partial[m][jc][i][50]  (fully overwritten every launch by the 1024 CTAs)
__device__ float g_partial[8 * 16 * NOBJ * 50];

// ---------------------------------------------------------------------------
// mma.m16n8k16 row.col f32.f16.f16.f32
// A frag (4 b32): a0=(row g, k=2t4,2t4+1) a1=(g+8, same) a2=(g, +8) a3=(g+8, +8)
// B frag (2 b32): b0=(k=2t4,2t4+1, n=g)   b1=(k=+8, n=g)
// C frag (4 f32): c0=(g, n=2t4) c1=(g, 2t4+1) c2=(g+8, 2t4) c3=(g+8, 2t4+1)
// ---------------------------------------------------------------------------
__device__ __forceinline__ void mma16816(float c[4], const uint32_t a[4],
                                         uint32_t b0, uint32_t b1)
{
    asm("mma.sync.aligned.m16n8k16.row.col.f32.f16.f16.f32 "
        "{%0,%1,%2,%3}, {%4,%5,%6,%7}, {%8,%9}, {%0,%1,%2,%3};\n"
        : "+f"(c[0]), "+f"(c[1]), "+f"(c[2]), "+f"(c[3])
        : "r"(a[0]), "r"(a[1]), "r"(a[2]), "r"(a[3]), "r"(b0), "r"(b1));
}

__device__ __forceinline__ uint32_t pack2(float x, float y)
{
    half2 h = __floats2half2_rn(x, y);
    return *reinterpret_cast<uint32_t*>(&h);
}

// relu on a packed half2 word: rn is monotone and rn(0)=0, so
// rn(max(v,0)) == max(rn(v),0) -- numerically identical to fp32 relu-then-pack.
__device__ __forceinline__ uint32_t relu2(uint32_t x)
{
    half2 h = *reinterpret_cast<half2*>(&x);
    half2 r = __hmax2(h, __floats2half2_rn(0.f, 0.f));
    return *reinterpret_cast<uint32_t*>(&r);
}

// dithered pair: w_e = rn(w); w_o = rn(2w - w_e)  (error of w_o ~ -error(w_e))
__device__ __forceinline__ void dither_w(float v, half& we, half& wo)
{
    we = __float2half_rn(v);
    wo = __float2half_rn(2.f * v - __half2float(we));
}

// k-interleaved SMEM slot for weight element at contraction index k (0..63):
// fragment thread t4 reads halfs {2t4, 2t4+1, 2t4+8, 2t4+9} of each 16-wide
// kt tile; store them contiguously so one v2 load fetches both b32 words.
__device__ __forceinline__ int kslot(int k)
{
    int kt = k >> 4, kk = k & 15;
    int t4s = (kk < 8) ? (kk >> 1) : ((kk - 8) >> 1);
    int c   = (kk < 8) ? (kk & 1)  : (2 + (kk & 1));
    return kt * 16 + t4s * 4 + c;
}

// one (jx, kt) chunk of the layer-1 rank-1 collapse -> 4 packed A-frag words.
// Emitted inside layer-3 tile bodies so its FMAs fill HMMA stall slots.
__device__ __forceinline__ void l1_chunk(
    int jj, int jx, int kt, const float* __restrict__ alph,
    const float (&pc)[16], const float (&qc)[16], const float (&rc)[16],
    float betaA, float betaB, uint32_t (&A2h)[2][4][4])
{
    const float al = alph[jj + jx];
    const int b = kt * 4;
    float u0 = fmaf(al, pc[b + 0], rc[b + 0]);
    float u1 = fmaf(al, pc[b + 1], rc[b + 1]);
    float u2 = fmaf(al, pc[b + 2], rc[b + 2]);
    float u3 = fmaf(al, pc[b + 3], rc[b + 3]);
    A2h[jx][kt][0] = relu2(pack2(fmaf(betaA, qc[b + 0], u0),
                                 fmaf(betaA, qc[b + 1], u1)));
    A2h[jx][kt][1] = relu2(pack2(fmaf(betaB, qc[b + 0], u0),
                                 fmaf(betaB, qc[b + 1], u1)));
    A2h[jx][kt][2] = relu2(pack2(fmaf(betaA, qc[b + 2], u2),
                                 fmaf(betaA, qc[b + 3], u3)));
    A2h[jx][kt][3] = relu2(pack2(fmaf(betaB, qc[b + 2], u2),
                                 fmaf(betaB, qc[b + 3], u3)));
}

__global__ void __launch_bounds__(TPB, 1)
pair_kernel(const float* __restrict__ obj0, const float* __restrict__ obj1,
            const float* __restrict__ prev0, const float* __restrict__ prev1,
            const float* __restrict__ gW0, const float* __restrict__ gb0,
            const float* __restrict__ gW1, const float* __restrict__ gb1,
            const float* __restrict__ gW2, const float* __restrict__ gb2)
{
    const int m  = blockIdx.x;   // module (actor class = m>>1, actee class = m&1)
    const int ib = blockIdx.y;   // i-block (128 actees)
    const int jc = blockIdx.z;   // j-chunk (64 actors, 16 chunks)
    const int t  = threadIdx.x;
    const int w  = t >> 5;
    const int lane = t & 31;
    const int t4 = lane & 3;
    const int g  = lane >> 2;

    const int ac = m >> 1;
    const float* actor = (ac == 0) ? obj0 : (ac == 1) ? obj1 : (ac == 2) ? prev0 : prev1;
    const float* actee = (m & 1) ? obj1 : obj0;

    // Interleaved transposed weights; row k=50 carries the bias (fed by the
    // constant-1.0 col-50 of H). Even/odd dithered copies selected by PAIR
    // parity so a j-pair shares its B loads.
    __shared__ alignas(16) half Wt1e[64 * WST], Wt1o[64 * WST];
    __shared__ alignas(16) half Wt2e[64 * WST], Wt2o[64 * WST];
    __shared__ float alph[JB];

    for (int x = t; x < 64 * WST; x += TPB) {
        Wt1e[x] = __float2half(0.f);  Wt1o[x] = __float2half(0.f);
        Wt2e[x] = __float2half(0.f);  Wt2o[x] = __float2half(0.f);
    }
    __syncthreads();
    for (int x = t; x < 51 * 50; x += TPB) {
        int k = x / 50, n = x % 50;
        int s = n * WST + kslot(k);
        float w1 = (k < 50) ? gW1[m * 2500 + k * 50 + n] : gb1[m * 50 + n];
        float w2 = (k < 50) ? gW2[m * 2500 + k * 50 + n] : gb2[m * 50 + n];
        half we, wo;
        dither_w(w1, we, wo);  Wt1e[s] = we;  Wt1o[s] = wo;
        dither_w(w2, we, wo);  Wt2e[s] = we;  Wt2o[s] = wo;
    }
    if (t < JB) alph[t] = actor[jc * JB + t];

    // per-thread layer-1 constants at this thread's 16 fragment columns
    float pc[16], qc[16], rc[16];
#pragma unroll
    for (int kt = 0; kt < 4; kt++)
#pragma unroll
        for (int s = 0; s < 4; s++) {
            int col = kt * 16 + 2 * t4 + ((s >> 1) << 3) + (s & 1);
            int idx = kt * 4 + s;
            pc[idx] = (col < 50) ? gW0[m * 100 + col] : 0.f;        // W0[m][0][col]
            qc[idx] = (col < 50) ? gW0[m * 100 + 50 + col] : 0.f;   // W0[m][1][col]
            rc[idx] = (col < 50) ? gb0[m * 50 + col]
                                 : (col == 50 ? 1.f : 0.f);          // bias-feed col
        }
    const float betaA = actee[ib * 128 + w * 16 + g];
    const float betaB = actee[ib * 128 + w * 16 + g + 8];

    float Fr[28];
#pragma unroll
    for (int x = 0; x < 28; x++) Fr[x] = 0.f;

    // A3 kt=3 upper slots (k=56..63) always zero: nt=7 trimmed away
    uint32_t A3h[2][4][4];
    A3h[0][3][2] = A3h[0][3][3] = A3h[1][3][2] = A3h[1][3][3] = 0u;

    __syncthreads();    // the ONLY barrier before the writeback

    // prologue: layer-1 fragments for pair 0
    uint32_t A2h[2][4][4];
#pragma unroll
    for (int c = 0; c < 8; c++)
        l1_chunk(0, c >> 2, c & 3, alph, pc, qc, rc, betaA, betaB, A2h);

    for (int jj = 0; jj < JB; jj += 2) {
        // pair-parity dithered weight set (both j's of the pair share B loads)
        const int par = (jj >> 1) & 1;
        const half* __restrict__ W1 = par ? Wt1o : Wt1e;
        const half* __restrict__ W2 = par ? Wt2o : Wt2e;
        const int jn = (jj + 2 < JB) ? jj + 2 : 0;   // next pair (dummy on last)

        // ---- layer 2: z2 = H1 @ W1d (+b1 via col-50 feed) -> A3 (both j) ----
        // nt = 0..6 (cols 56..63 all-zero). One v2 load feeds 2 MMAs.
#pragma unroll
        for (int nt = 0; nt < 7; nt++) {
            float c0[2][4] = {{0.f,0.f,0.f,0.f},{0.f,0.f,0.f,0.f}};
            float c1[2][4] = {{0.f,0.f,0.f,0.f},{0.f,0.f,0.f,0.f}};
            const int ro = (nt * 8 + g) * WST + t4 * 4;
#pragma unroll
            for (int kt = 0; kt < 4; kt++) {
                uint2 bb = *(const uint2*)(W1 + ro + kt * 16);
                mma16816((kt < 2) ? c0[0] : c1[0], A2h[0][kt], bb.x, bb.y);
                mma16816((kt < 2) ? c0[1] : c1[1], A2h[1][kt], bb.x, bb.y);
            }
            const int kt2 = nt >> 1, s0 = (nt & 1) ? 2 : 0;
            if (nt != 6) {
#pragma unroll
                for (int jx = 0; jx < 2; jx++) {
                    A3h[jx][kt2][s0]     = relu2(pack2(c0[jx][0] + c1[jx][0],
                                                       c0[jx][1] + c1[jx][1]));
                    A3h[jx][kt2][s0 + 1] = relu2(pack2(c0[jx][2] + c1[jx][2],
                                                       c0[jx][3] + c1[jx][3]));
                }
            } else {   // cols 48..55: col 50 is the constant-1.0 bias feed
                const int col0 = 48 + 2 * t4;
#pragma unroll
                for (int jx = 0; jx < 2; jx++) {
                    float v0 = (col0 == 50) ? 1.f : fmaxf(c0[jx][0] + c1[jx][0], 0.f);
                    float v1 = fmaxf(c0[jx][1] + c1[jx][1], 0.f);   // odd col, never 50
                    float v2 = (col0 == 50) ? 1.f : fmaxf(c0[jx][2] + c1[jx][2], 0.f);
                    float v3 = fmaxf(c0[jx][3] + c1[jx][3], 0.f);
                    A3h[jx][3][0] = pack2(v0, v1);
                    A3h[jx][3][1] = pack2(v2, v3);
                }
            }
        }
        // A2h (pair jj) is now dead — its registers are recycled below for
        // pair jn, interleaved into layer-3's HMMA stall shadow.

        // ---- layer 3: z3 = H2 @ W2d (+b2), relu, accum; + L1(next) chunks ----
#pragma unroll
        for (int nt = 0; nt < 7; nt++) {
            float c0[2][4] = {{0.f,0.f,0.f,0.f},{0.f,0.f,0.f,0.f}};
            float c1[2][4] = {{0.f,0.f,0.f,0.f},{0.f,0.f,0.f,0.f}};
            const int ro = (nt * 8 + g) * WST + t4 * 4;
#pragma unroll
            for (int kt = 0; kt < 4; kt++) {
                uint2 bb = *(const uint2*)(W2 + ro + kt * 16);
                mma16816((kt < 2) ? c0[0] : c1[0], A3h[0][kt], bb.x, bb.y);
                mma16816((kt < 2) ? c0[1] : c1[1], A3h[1][kt], bb.x, bb.y);
            }
            // next pair's layer-1 chunk: independent work to fill MMA waits
            l1_chunk(jn, nt >> 2, nt & 3, alph, pc, qc, rc, betaA, betaB, A2h);
#pragma unroll
            for (int jx = 0; jx < 2; jx++) {
                Fr[nt * 4 + 0] += fmaxf(c0[jx][0] + c1[jx][0], 0.f);
                Fr[nt * 4 + 1] += fmaxf(c0[jx][1] + c1[jx][1], 0.f);
                Fr[nt * 4 + 2] += fmaxf(c0[jx][2] + c1[jx][2], 0.f);
                Fr[nt * 4 + 3] += fmaxf(c0[jx][3] + c1[jx][3], 0.f);
            }
        }
        l1_chunk(jn, 1, 3, alph, pc, qc, rc, betaA, betaB, A2h);  // 8th chunk
    }

    // ---- deterministic partial writeback (W3 folded post-sum in finalize) ----
    const int i0 = ib * 128 + w * 16 + g;
    const long base = (long)(m * 16 + jc) * NOBJ;
#pragma unroll
    for (int nt = 0; nt < 7; nt++) {
        const int col0 = nt * 8 + 2 * t4;
        if (col0 < 50) {
            g_partial[(base + i0) * 50 + col0]     = Fr[nt * 4 + 0];
            g_partial[(base + i0 + 8) * 50 + col0] = Fr[nt * 4 + 2];
        }
        if (col0 + 1 < 50) {
            g_partial[(base + i0) * 50 + col0 + 1]     = Fr[nt * 4 + 1];
            g_partial[(base + i0 + 8) * 50 + col0 + 1] = Fr[nt * 4 + 3];
        }
    }
}

// warp-per-(c,i) finalize: jc-reduce, fold W3, apply head MLP
__global__ void __launch_bounds__(256)
finalize_kernel(const float* __restrict__ gW3, const float* __restrict__ gb3,
                const float* __restrict__ aW0, const float* __restrict__ ab0,
                const float* __restrict__ aW1, const float* __restrict__ ab1,
                float* __restrict__ out)
{
    const int warp = blockIdx.x * (blockDim.x >> 5) + (threadIdx.x >> 5);
    const int lane = threadIdx.x & 31;

    if (warp >= 2048) return;
    const int c = warp >> 10;
    const int i = warp & 1023;

    float F[20];
#pragma unroll
    for (int o = 0; o < 20; o++) F[o] = 0.f;

    for (int idx = lane; idx < 200; idx += 32) {
        const int a = idx / 50, k = idx % 50;
        const int mm = a * 2 + c;
        const float* gp = g_partial + ((long)(mm * 16) * NOBJ + i) * 50 + k;
        float s = 0.f;
#pragma unroll
        for (int jcc = 0; jcc < 16; jcc++) s += gp[(long)jcc * NOBJ * 50];
        const float* w3 = gW3 + mm * 1000 + k * 20;
#pragma unroll
        for (int o = 0; o < 20; o++) F[o] = fmaf(s, w3[o], F[o]);
    }
#pragma unroll
    for (int off = 16; off; off >>= 1)
#pragma unroll
        for (int o = 0; o < 20; o++)
            F[o] += __shfl_xor_sync(0xffffffffu, F[o], off);
#pragma unroll
    for (int o = 0; o < 20; o++) {
        float b = gb3[(0 + c) * 20 + o] + gb3[(2 + c) * 20 + o]
                + gb3[(4 + c) * 20 + o] + gb3[(6 + c) * 20 + o];
        F[o] += 1024.f * b;
    }

    float p = 0.f;
    for (int l = lane; l < 50; l += 32) {
        float h = ab0[c * 50 + l];
#pragma unroll
        for (int o = 0; o < 20; o++)
            h = fmaf(F[o], aW0[c * 1000 + o * 50 + l], h);
        p = fmaf(fmaxf(h, 0.f), aW1[c * 50 + l], p);
    }
#pragma unroll
    for (int off = 16; off; off >>= 1)
        p += __shfl_xor_sync(0xffffffffu, p, off);
    if (lane == 0) out[c * 1024 + i] = p + ab1[c];
}

extern "C" void kernel_launch(void* const* d_in, const int* in_sizes, int n_in,
                              void* d_out, int out_size)
{
    const float* obj0  = (const float*)d_in[0];
    const float* obj1  = (const float*)d_in[1];
    const float* prev0 = (const float*)d_in[2];
    const float* prev1 = (const float*)d_in[3];
    const float* gW0   = (const float*)d_in[4];
    const float* gb0   = (const float*)d_in[5];
    const float* gW1   = (const float*)d_in[6];
    const float* gb1   = (const float*)d_in[7];
    const float* gW2   = (const float*)d_in[8];
    const float* gb2   = (const float*)d_in[9];
    const float* gW3   = (const float*)d_in[10];
    const float* gb3   = (const float*)d_in[11];
    const float* aW0   = (const float*)d_in[12];
    const float* ab0   = (const float*)d_in[13];
    const float* aW1   = (const float*)d_in[14];
    const float* ab1   = (const float*)d_in[15];

    dim3 grid(8, 8, 16);   // (module, i-block, j-chunk of 64) -> 1024 CTAs
    pair_kernel<<<grid, TPB>>>(obj0, obj1, prev0, prev1,
                               gW0, gb0, gW1, gb1, gW2, gb2);
    finalize_kernel<<<256, 256>>>(gW3, gb3, aW0, ab0, aW1, ab1, (float*)d_out);
}

// round 15
// speedup vs baseline: 1.0407x; 1.0407x over previous
#include <cuda_runtime.h>
#include <cuda_fp16.h>
#include <cstdint>

#define NOBJ 1024
#define TPB  256
#define JB   64        // actors per CTA chunk (16 chunks -> 1024 CTAs, 7 waves)
#define WST  80        // SMEM weight row stride (halfs): 160B == 32 mod 128
                       // -> conflict-free ld.shared.v2.u32 of B fragments

// partial[m][jc][i][50]  (fully overwritten every launch by the 1024 CTAs)
__device__ float g_partial[8 * 16 * NOBJ * 50];

// ---------------------------------------------------------------------------
// mma.m16n8k16 row.col f32.f16.f16.f32
// A frag (4 b32): a0=(row g, k=2t4,2t4+1) a1=(g+8, same) a2=(g, +8) a3=(g+8, +8)
// B frag (2 b32): b0=(k=2t4,2t4+1, n=g)   b1=(k=+8, n=g)
// C frag (4 f32): c0=(g, n=2t4) c1=(g, 2t4+1) c2=(g+8, 2t4) c3=(g+8, 2t4+1)
// ---------------------------------------------------------------------------
__device__ __forceinline__ void mma16816(float c[4], const uint32_t a[4],
                                         uint32_t b0, uint32_t b1)
{
    asm("mma.sync.aligned.m16n8k16.row.col.f32.f16.f16.f32 "
        "{%0,%1,%2,%3}, {%4,%5,%6,%7}, {%8,%9}, {%0,%1,%2,%3};\n"
        : "+f"(c[0]), "+f"(c[1]), "+f"(c[2]), "+f"(c[3])
        : "r"(a[0]), "r"(a[1]), "r"(a[2]), "r"(a[3]), "r"(b0), "r"(b1));
}

// m16n8k8: A frag 2 regs (a0=(row g, k=2t4,2t4+1), a1=(g+8, same)), B frag 1 reg
__device__ __forceinline__ void mma16808(float c[4], uint32_t a0, uint32_t a1,
                                         uint32_t b0)
{
    asm("mma.sync.aligned.m16n8k8.row.col.f32.f16.f16.f32 "
        "{%0,%1,%2,%3}, {%4,%5}, {%6}, {%0,%1,%2,%3};\n"
        : "+f"(c[0]), "+f"(c[1]), "+f"(c[2]), "+f"(c[3])
        : "r"(a0), "r"(a1), "r"(b0));
}

__device__ __forceinline__ uint32_t pack2(float x, float y)
{
    half2 h = __floats2half2_rn(x, y);
    return *reinterpret_cast<uint32_t*>(&h);
}

// relu on a packed half2 word: rn is monotone and rn(0)=0, so
// rn(max(v,0)) == max(rn(v),0) -- numerically identical to fp32 relu-then-pack.
__device__ __forceinline__ uint32_t relu2(uint32_t x)
{
    half2 h = *reinterpret_cast<half2*>(&x);
    half2 r = __hmax2(h, __floats2half2_rn(0.f, 0.f));
    return *reinterpret_cast<uint32_t*>(&r);
}

// dithered pair: w_e = rn(w); w_o = rn(2w - w_e)  (error of w_o ~ -error(w_e))
__device__ __forceinline__ void dither_w(float v, half& we, half& wo)
{
    we = __float2half_rn(v);
    wo = __float2half_rn(2.f * v - __half2float(we));
}

// k-interleaved SMEM slot for weight element at contraction index k (0..63):
// fragment thread t4 reads halfs {2t4, 2t4+1, 2t4+8, 2t4+9} of each 16-wide
// kt tile; store them contiguously so one v2 load fetches both b32 words.
__device__ __forceinline__ int kslot(int k)
{
    int kt = k >> 4, kk = k & 15;
    int t4s = (kk < 8) ? (kk >> 1) : ((kk - 8) >> 1);
    int c   = (kk < 8) ? (kk & 1)  : (2 + (kk & 1));
    return kt * 16 + t4s * 4 + c;
}

__global__ void __launch_bounds__(TPB, 1)
pair_kernel(const float* __restrict__ obj0, const float* __restrict__ obj1,
            const float* __restrict__ prev0, const float* __restrict__ prev1,
            const float* __restrict__ gW0, const float* __restrict__ gb0,
            const float* __restrict__ gW1, const float* __restrict__ gb1,
            const float* __restrict__ gW2, const float* __restrict__ gb2)
{
    const int m  = blockIdx.x;   // module (actor class = m>>1, actee class = m&1)
    const int ib = blockIdx.y;   // i-block (128 actees)
    const int jc = blockIdx.z;   // j-chunk (64 actors, 16 chunks)
    const int t  = threadIdx.x;
    const int w  = t >> 5;
    const int lane = t & 31;
    const int t4 = lane & 3;
    const int g  = lane >> 2;

    const int ac = m >> 1;
    const float* actor = (ac == 0) ? obj0 : (ac == 1) ? obj1 : (ac == 2) ? prev0 : prev1;
    const float* actee = (m & 1) ? obj1 : obj0;

    // Interleaved transposed weights; row k=50 carries the bias (fed by the
    // constant-1.0 col-50 of H). Even/odd dithered copies selected by PAIR
    // parity so a j-pair shares its B loads.
    __shared__ alignas(16) half Wt1e[64 * WST], Wt1o[64 * WST];
    __shared__ alignas(16) half Wt2e[64 * WST], Wt2o[64 * WST];
    __shared__ float alph[JB];

    for (int x = t; x < 64 * WST; x += TPB) {
        Wt1e[x] = __float2half(0.f);  Wt1o[x] = __float2half(0.f);
        Wt2e[x] = __float2half(0.f);  Wt2o[x] = __float2half(0.f);
    }
    __syncthreads();
    for (int x = t; x < 51 * 50; x += TPB) {
        int k = x / 50, n = x % 50;
        int s = n * WST + kslot(k);
        float w1 = (k < 50) ? gW1[m * 2500 + k * 50 + n] : gb1[m * 50 + n];
        float w2 = (k < 50) ? gW2[m * 2500 + k * 50 + n] : gb2[m * 50 + n];
        half we, wo;
        dither_w(w1, we, wo);  Wt1e[s] = we;  Wt1o[s] = wo;
        dither_w(w2, we, wo);  Wt2e[s] = we;  Wt2o[s] = wo;
    }
    if (t < JB) alph[t] = actor[jc * JB + t];

    // per-thread layer-1 constants at this thread's 16 fragment columns
    // (kt=3 upper slots k=56..63 are never used: m16n8k8 covers only 48..55)
    float pc[16], qc[16], rc[16];
#pragma unroll
    for (int kt = 0; kt < 4; kt++)
#pragma unroll
        for (int s = 0; s < 4; s++) {
            int col = kt * 16 + 2 * t4 + ((s >> 1) << 3) + (s & 1);
            int idx = kt * 4 + s;
            pc[idx] = (col < 50) ? gW0[m * 100 + col] : 0.f;        // W0[m][0][col]
            qc[idx] = (col < 50) ? gW0[m * 100 + 50 + col] : 0.f;   // W0[m][1][col]
            rc[idx] = (col < 50) ? gb0[m * 50 + col]
                                 : (col == 50 ? 1.f : 0.f);          // bias-feed col
        }
    const float betaA = actee[ib * 128 + w * 16 + g];
    const float betaB = actee[ib * 128 + w * 16 + g + 8];

    float Fr[28];
#pragma unroll
    for (int x = 0; x < 28; x++) Fr[x] = 0.f;

    uint32_t A3h[2][4][4];   // [·][3][2..3] unused (k 56..63 handled by k8 MMA)

    __syncthreads();    // the ONLY barrier before the writeback

    for (int jj = 0; jj < JB; jj += 2) {
        // pair-parity dithered weight set (both j's of the pair share B loads)
        const int par = (jj >> 1) & 1;
        const half* __restrict__ W1 = par ? Wt1o : Wt1e;
        const half* __restrict__ W2 = par ? Wt2o : Wt2e;

        // ---- layer 1 (rank-1 collapse) -> A fragments for both j's ----
        // kt=3: only the low k-half (48..55) is needed (k8 MMA).
        uint32_t A2h[2][4][4];
#pragma unroll
        for (int jx = 0; jx < 2; jx++) {
            const float al = alph[jj + jx];
#pragma unroll
            for (int kt = 0; kt < 4; kt++) {
                const int b = kt * 4;
                float u0 = fmaf(al, pc[b + 0], rc[b + 0]);
                float u1 = fmaf(al, pc[b + 1], rc[b + 1]);
                A2h[jx][kt][0] = relu2(pack2(fmaf(betaA, qc[b + 0], u0),
                                             fmaf(betaA, qc[b + 1], u1)));
                A2h[jx][kt][1] = relu2(pack2(fmaf(betaB, qc[b + 0], u0),
                                             fmaf(betaB, qc[b + 1], u1)));
                if (kt < 3) {
                    float u2 = fmaf(al, pc[b + 2], rc[b + 2]);
                    float u3 = fmaf(al, pc[b + 3], rc[b + 3]);
                    A2h[jx][kt][2] = relu2(pack2(fmaf(betaA, qc[b + 2], u2),
                                                 fmaf(betaA, qc[b + 3], u3)));
                    A2h[jx][kt][3] = relu2(pack2(fmaf(betaB, qc[b + 2], u2),
                                                 fmaf(betaB, qc[b + 3], u3)));
                }
            }
        }

        // ---- layer 2: z2 = H1 @ W1d (+b1 via col-50 feed) -> A3 (both j) ----
        // nt = 0..6 (cols 56..63 all-zero). kt 0..2: k16; kt 3: k8 (k 48..55).
#pragma unroll
        for (int nt = 0; nt < 7; nt++) {
            float c0[2][4] = {{0.f,0.f,0.f,0.f},{0.f,0.f,0.f,0.f}};
            float c1[2][4] = {{0.f,0.f,0.f,0.f},{0.f,0.f,0.f,0.f}};
            const int ro = (nt * 8 + g) * WST + t4 * 4;
#pragma unroll
            for (int kt = 0; kt < 3; kt++) {
                uint2 bb = *(const uint2*)(W1 + ro + kt * 16);
                mma16816((kt < 2) ? c0[0] : c1[0], A2h[0][kt], bb.x, bb.y);
                mma16816((kt < 2) ? c0[1] : c1[1], A2h[1][kt], bb.x, bb.y);
            }
            {
                uint32_t b0 = *(const uint32_t*)(W1 + ro + 48);
                mma16808(c1[0], A2h[0][3][0], A2h[0][3][1], b0);
                mma16808(c1[1], A2h[1][3][0], A2h[1][3][1], b0);
            }
            const int kt2 = nt >> 1, s0 = (nt & 1) ? 2 : 0;
            if (nt != 6) {
#pragma unroll
                for (int jx = 0; jx < 2; jx++) {
                    A3h[jx][kt2][s0]     = relu2(pack2(c0[jx][0] + c1[jx][0],
                                                       c0[jx][1] + c1[jx][1]));
                    A3h[jx][kt2][s0 + 1] = relu2(pack2(c0[jx][2] + c1[jx][2],
                                                       c0[jx][3] + c1[jx][3]));
                }
            } else {   // cols 48..55: col 50 is the constant-1.0 bias feed
                const int col0 = 48 + 2 * t4;
#pragma unroll
                for (int jx = 0; jx < 2; jx++) {
                    float v0 = (col0 == 50) ? 1.f : fmaxf(c0[jx][0] + c1[jx][0], 0.f);
                    float v1 = fmaxf(c0[jx][1] + c1[jx][1], 0.f);   // odd col, never 50
                    float v2 = (col0 == 50) ? 1.f : fmaxf(c0[jx][2] + c1[jx][2], 0.f);
                    float v3 = fmaxf(c0[jx][3] + c1[jx][3], 0.f);
                    A3h[jx][3][0] = pack2(v0, v1);
                    A3h[jx][3][1] = pack2(v2, v3);
                }
            }
        }

        // ---- layer 3: z3 = H2 @ W2d (+b2 via col-50 feed), relu, accum ----
#pragma unroll
        for (int nt = 0; nt < 7; nt++) {
            float c0[2][4] = {{0.f,0.f,0.f,0.f},{0.f,0.f,0.f,0.f}};
            float c1[2][4] = {{0.f,0.f,0.f,0.f},{0.f,0.f,0.f,0.f}};
            const int ro = (nt * 8 + g) * WST + t4 * 4;
#pragma unroll
            for (int kt = 0; kt < 3; kt++) {
                uint2 bb = *(const uint2*)(W2 + ro + kt * 16);
                mma16816((kt < 2) ? c0[0] : c1[0], A3h[0][kt], bb.x, bb.y);
                mma16816((kt < 2) ? c0[1] : c1[1], A3h[1][kt], bb.x, bb.y);
            }
            {
                uint32_t b0 = *(const uint32_t*)(W2 + ro + 48);
                mma16808(c1[0], A3h[0][3][0], A3h[0][3][1], b0);
                mma16808(c1[1], A3h[1][3][0], A3h[1][3][1], b0);
            }
#pragma unroll
            for (int jx = 0; jx < 2; jx++) {
                Fr[nt * 4 + 0] += fmaxf(c0[jx][0] + c1[jx][0], 0.f);
                Fr[nt * 4 + 1] += fmaxf(c0[jx][1] + c1[jx][1], 0.f);
                Fr[nt * 4 + 2] += fmaxf(c0[jx][2] + c1[jx][2], 0.f);
                Fr[nt * 4 + 3] += fmaxf(c0[jx][3] + c1[jx][3], 0.f);
            }
        }
    }

    // ---- deterministic partial writeback (W3 folded post-sum in finalize) ----
    const int i0 = ib * 128 + w * 16 + g;
    const long base = (long)(m * 16 + jc) * NOBJ;
#pragma unroll
    for (int nt = 0; nt < 7; nt++) {
        const int col0 = nt * 8 + 2 * t4;
        if (col0 < 50) {
            g_partial[(base + i0) * 50 + col0]     = Fr[nt * 4 + 0];
            g_partial[(base + i0 + 8) * 50 + col0] = Fr[nt * 4 + 2];
        }
        if (col0 + 1 < 50) {
            g_partial[(base + i0) * 50 + col0 + 1]     = Fr[nt * 4 + 1];
            g_partial[(base + i0 + 8) * 50 + col0 + 1] = Fr[nt * 4 + 3];
        }
    }
}

// warp-per-(c,i) finalize: jc-reduce, fold W3, apply head MLP
__global__ void __launch_bounds__(256)
finalize_kernel(const float* __restrict__ gW3, const float* __restrict__ gb3,
                const float* __restrict__ aW0, const float* __restrict__ ab0,
                const float* __restrict__ aW1, const float* __restrict__ ab1,
                float* __restrict__ out)
{
    const int warp = blockIdx.x * (blockDim.x >> 5) + (threadIdx.x >> 5);
    const int lane = threadIdx.x & 31;

    if (warp >= 2048) return;
    const int c = warp >> 10;
    const int i = warp & 1023;

    float F[20];
#pragma unroll
    for (int o = 0; o < 20; o++) F[o] = 0.f;

    for (int idx = lane; idx < 200; idx += 32) {
        const int a = idx / 50, k = idx % 50;
        const int mm = a * 2 + c;
        const float* gp = g_partial + ((long)(mm * 16) * NOBJ + i) * 50 + k;
        float s = 0.f;
#pragma unroll
        for (int jcc = 0; jcc < 16; jcc++) s += gp[(long)jcc * NOBJ * 50];
        const float* w3 = gW3 + mm * 1000 + k * 20;
#pragma unroll
        for (int o = 0; o < 20; o++) F[o] = fmaf(s, w3[o], F[o]);
    }
#pragma unroll
    for (int off = 16; off; off >>= 1)
#pragma unroll
        for (int o = 0; o < 20; o++)
            F[o] += __shfl_xor_sync(0xffffffffu, F[o], off);
#pragma unroll
    for (int o = 0; o < 20; o++) {
        float b = gb3[(0 + c) * 20 + o] + gb3[(2 + c) * 20 + o]
                + gb3[(4 + c) * 20 + o] + gb3[(6 + c) * 20 + o];
        F[o] += 1024.f * b;
    }

    float p = 0.f;
    for (int l = lane; l < 50; l += 32) {
        float h = ab0[c * 50 + l];
#pragma unroll
        for (int o = 0; o < 20; o++)
            h = fmaf(F[o], aW0[c * 1000 + o * 50 + l], h);
        p = fmaf(fmaxf(h, 0.f), aW1[c * 50 + l], p);
    }
#pragma unroll
    for (int off = 16; off; off >>= 1)
        p += __shfl_xor_sync(0xffffffffu, p, off);
    if (lane == 0) out[c * 1024 + i] = p + ab1[c];
}

extern "C" void kernel_launch(void* const* d_in, const int* in_sizes, int n_in,
                              void* d_out, int out_size)
{
    const float* obj0  = (const float*)d_in[0];
    const float* obj1  = (const float*)d_in[1];
    const float* prev0 = (const float*)d_in[2];
    const float* prev1 = (const float*)d_in[3];
    const float* gW0   = (const float*)d_in[4];
    const float* gb0   = (const float*)d_in[5];
    const float* gW1   = (const float*)d_in[6];
    const float* gb1   = (const float*)d_in[7];
    const float* gW2   = (const float*)d_in[8];
    const float* gb2   = (const float*)d_in[9];
    const float* gW3   = (const float*)d_in[10];
    const float* gb3   = (const float*)d_in[11];
    const float* aW0   = (const float*)d_in[12];
    const float* ab0   = (const float*)d_in[13];
    const float* aW1   = (const float*)d_in[14];
    const float* ab1   = (const float*)d_in[15];

    dim3 grid(8, 8, 16);   // (module, i-block, j-chunk of 64) -> 1024 CTAs
    pair_kernel<<<grid, TPB>>>(obj0, obj1, prev0, prev1,
                               gW0, gb0, gW1, gb1, gW2, gb2);
    finalize_kernel<<<256, 256>>>(gW3, gb3, aW0, ab0, aW1, ab1, (float*)d_out);
}

// round 16
// speedup vs baseline: 1.0475x; 1.0066x over previous
#include <cuda_runtime.h>
#include <cuda_fp16.h>
#include <cstdint>

#define NOBJ 1024
#define TPB  256
#define JB   64        // actors per CTA chunk (16 chunks -> 1024 CTAs, 7 waves)
#define WST  80        // SMEM weight row stride (halfs): 160B == 32 mod 128
                       // -> conflict-free ld.shared.v2.u32 of B fragments

// partial[m][jc][i][25] as packed half2 pairs (cols 2p, 2p+1).
// Fully overwritten every launch by the 1024 CTAs.
__device__ uint32_t g_partial[8 * 16 * NOBJ * 25];

// ---------------------------------------------------------------------------
// mma.m16n8k16 row.col f32.f16.f16.f32
// A frag (4 b32): a0=(row g, k=2t4,2t4+1) a1=(g+8, same) a2=(g, +8) a3=(g+8, +8)
// B frag (2 b32): b0=(k=2t4,2t4+1, n=g)   b1=(k=+8, n=g)
// C frag (4 f32): c0=(g, n=2t4) c1=(g, 2t4+1) c2=(g+8, 2t4) c3=(g+8, 2t4+1)
// ---------------------------------------------------------------------------
__device__ __forceinline__ void mma16816(float c[4], const uint32_t a[4],
                                         uint32_t b0, uint32_t b1)
{
    asm("mma.sync.aligned.m16n8k16.row.col.f32.f16.f16.f32 "
        "{%0,%1,%2,%3}, {%4,%5,%6,%7}, {%8,%9}, {%0,%1,%2,%3};\n"
        : "+f"(c[0]), "+f"(c[1]), "+f"(c[2]), "+f"(c[3])
        : "r"(a[0]), "r"(a[1]), "r"(a[2]), "r"(a[3]), "r"(b0), "r"(b1));
}

// m16n8k8: A frag 2 regs (a0=(row g, k=2t4,2t4+1), a1=(g+8, same)), B frag 1 reg
__device__ __forceinline__ void mma16808(float c[4], uint32_t a0, uint32_t a1,
                                         uint32_t b0)
{
    asm("mma.sync.aligned.m16n8k8.row.col.f32.f16.f16.f32 "
        "{%0,%1,%2,%3}, {%4,%5}, {%6}, {%0,%1,%2,%3};\n"
        : "+f"(c[0]), "+f"(c[1]), "+f"(c[2]), "+f"(c[3])
        : "r"(a0), "r"(a1), "r"(b0));
}

__device__ __forceinline__ uint32_t pack2(float x, float y)
{
    half2 h = __floats2half2_rn(x, y);
    return *reinterpret_cast<uint32_t*>(&h);
}

// relu on a packed half2 word: rn is monotone and rn(0)=0, so
// rn(max(v,0)) == max(rn(v),0) -- numerically identical to fp32 relu-then-pack.
__device__ __forceinline__ uint32_t relu2(uint32_t x)
{
    half2 h = *reinterpret_cast<half2*>(&x);
    half2 r = __hmax2(h, __floats2half2_rn(0.f, 0.f));
    return *reinterpret_cast<uint32_t*>(&r);
}

// dithered pair: w_e = rn(w); w_o = rn(2w - w_e)  (error of w_o ~ -error(w_e))
__device__ __forceinline__ void dither_w(float v, half& we, half& wo)
{
    we = __float2half_rn(v);
    wo = __float2half_rn(2.f * v - __half2float(we));
}

// k-interleaved SMEM slot for weight element at contraction index k (0..63):
// fragment thread t4 reads halfs {2t4, 2t4+1, 2t4+8, 2t4+9} of each 16-wide
// kt tile; store them contiguously so one v2 load fetches both b32 words.
__device__ __forceinline__ int kslot(int k)
{
    int kt = k >> 4, kk = k & 15;
    int t4s = (kk < 8) ? (kk >> 1) : ((kk - 8) >> 1);
    int c   = (kk < 8) ? (kk & 1)  : (2 + (kk & 1));
    return kt * 16 + t4s * 4 + c;
}

__global__ void __launch_bounds__(TPB, 1)
pair_kernel(const float* __restrict__ obj0, const float* __restrict__ obj1,
            const float* __restrict__ prev0, const float* __restrict__ prev1,
            const float* __restrict__ gW0, const float* __restrict__ gb0,
            const float* __restrict__ gW1, const float* __restrict__ gb1,
            const float* __restrict__ gW2, const float* __restrict__ gb2)
{
    const int m  = blockIdx.x;   // module (actor class = m>>1, actee class = m&1)
    const int ib = blockIdx.y;   // i-block (128 actees)
    const int jc = blockIdx.z;   // j-chunk (64 actors, 16 chunks)
    const int t  = threadIdx.x;
    const int w  = t >> 5;
    const int lane = t & 31;
    const int t4 = lane & 3;
    const int g  = lane >> 2;

    const int ac = m >> 1;
    const float* actor = (ac == 0) ? obj0 : (ac == 1) ? obj1 : (ac == 2) ? prev0 : prev1;
    const float* actee = (m & 1) ? obj1 : obj0;

    // Interleaved transposed weights; row k=50 carries the bias (fed by the
    // constant-1.0 col-50 of H). Even/odd dithered copies selected by PAIR
    // parity so a j-pair shares its B loads.
    __shared__ alignas(16) half Wt1e[64 * WST], Wt1o[64 * WST];
    __shared__ alignas(16) half Wt2e[64 * WST], Wt2o[64 * WST];
    __shared__ float alph[JB];

    for (int x = t; x < 64 * WST; x += TPB) {
        Wt1e[x] = __float2half(0.f);  Wt1o[x] = __float2half(0.f);
        Wt2e[x] = __float2half(0.f);  Wt2o[x] = __float2half(0.f);
    }
    __syncthreads();
    for (int x = t; x < 51 * 50; x += TPB) {
        int k = x / 50, n = x % 50;
        int s = n * WST + kslot(k);
        float w1 = (k < 50) ? gW1[m * 2500 + k * 50 + n] : gb1[m * 50 + n];
        float w2 = (k < 50) ? gW2[m * 2500 + k * 50 + n] : gb2[m * 50 + n];
        half we, wo;
        dither_w(w1, we, wo);  Wt1e[s] = we;  Wt1o[s] = wo;
        dither_w(w2, we, wo);  Wt2e[s] = we;  Wt2o[s] = wo;
    }
    if (t < JB) alph[t] = actor[jc * JB + t];

    // per-thread layer-1 constants at this thread's 16 fragment columns
    // (kt=3 upper slots k=56..63 are never used: m16n8k8 covers only 48..55)
    float pc[16], qc[16], rc[16];
#pragma unroll
    for (int kt = 0; kt < 4; kt++)
#pragma unroll
        for (int s = 0; s < 4; s++) {
            int col = kt * 16 + 2 * t4 + ((s >> 1) << 3) + (s & 1);
            int idx = kt * 4 + s;
            pc[idx] = (col < 50) ? gW0[m * 100 + col] : 0.f;        // W0[m][0][col]
            qc[idx] = (col < 50) ? gW0[m * 100 + 50 + col] : 0.f;   // W0[m][1][col]
            rc[idx] = (col < 50) ? gb0[m * 50 + col]
                                 : (col == 50 ? 1.f : 0.f);          // bias-feed col
        }
    const float betaA = actee[ib * 128 + w * 16 + g];
    const float betaB = actee[ib * 128 + w * 16 + g + 8];

    float Fr[28];
#pragma unroll
    for (int x = 0; x < 28; x++) Fr[x] = 0.f;

    uint32_t A3h[2][4][4];   // [·][3][2..3] unused (k 56..63 handled by k8 MMA)

    __syncthreads();    // the ONLY barrier before the writeback

    for (int jj = 0; jj < JB; jj += 2) {
        // pair-parity dithered weight set (both j's of the pair share B loads)
        const int par = (jj >> 1) & 1;
        const half* __restrict__ W1 = par ? Wt1o : Wt1e;
        const half* __restrict__ W2 = par ? Wt2o : Wt2e;

        // ---- layer 1 (rank-1 collapse) -> A fragments for both j's ----
        // kt=3: only the low k-half (48..55) is needed (k8 MMA).
        uint32_t A2h[2][4][4];
#pragma unroll
        for (int jx = 0; jx < 2; jx++) {
            const float al = alph[jj + jx];
#pragma unroll
            for (int kt = 0; kt < 4; kt++) {
                const int b = kt * 4;
                float u0 = fmaf(al, pc[b + 0], rc[b + 0]);
                float u1 = fmaf(al, pc[b + 1], rc[b + 1]);
                A2h[jx][kt][0] = relu2(pack2(fmaf(betaA, qc[b + 0], u0),
                                             fmaf(betaA, qc[b + 1], u1)));
                A2h[jx][kt][1] = relu2(pack2(fmaf(betaB, qc[b + 0], u0),
                                             fmaf(betaB, qc[b + 1], u1)));
                if (kt < 3) {
                    float u2 = fmaf(al, pc[b + 2], rc[b + 2]);
                    float u3 = fmaf(al, pc[b + 3], rc[b + 3]);
                    A2h[jx][kt][2] = relu2(pack2(fmaf(betaA, qc[b + 2], u2),
                                                 fmaf(betaA, qc[b + 3], u3)));
                    A2h[jx][kt][3] = relu2(pack2(fmaf(betaB, qc[b + 2], u2),
                                                 fmaf(betaB, qc[b + 3], u3)));
                }
            }
        }

        // ---- layer 2: z2 = H1 @ W1d (+b1 via col-50 feed) -> A3 (both j) ----
        // nt = 0..6 (cols 56..63 all-zero). kt 0..2: k16; kt 3: k8 (k 48..55).
#pragma unroll
        for (int nt = 0; nt < 7; nt++) {
            float c0[2][4] = {{0.f,0.f,0.f,0.f},{0.f,0.f,0.f,0.f}};
            float c1[2][4] = {{0.f,0.f,0.f,0.f},{0.f,0.f,0.f,0.f}};
            const int ro = (nt * 8 + g) * WST + t4 * 4;
#pragma unroll
            for (int kt = 0; kt < 3; kt++) {
                uint2 bb = *(const uint2*)(W1 + ro + kt * 16);
                mma16816((kt < 2) ? c0[0] : c1[0], A2h[0][kt], bb.x, bb.y);
                mma16816((kt < 2) ? c0[1] : c1[1], A2h[1][kt], bb.x, bb.y);
            }
            {
                uint32_t b0 = *(const uint32_t*)(W1 + ro + 48);
                mma16808(c1[0], A2h[0][3][0], A2h[0][3][1], b0);
                mma16808(c1[1], A2h[1][3][0], A2h[1][3][1], b0);
            }
            const int kt2 = nt >> 1, s0 = (nt & 1) ? 2 : 0;
            if (nt != 6) {
#pragma unroll
                for (int jx = 0; jx < 2; jx++) {
                    A3h[jx][kt2][s0]     = relu2(pack2(c0[jx][0] + c1[jx][0],
                                                       c0[jx][1] + c1[jx][1]));
                    A3h[jx][kt2][s0 + 1] = relu2(pack2(c0[jx][2] + c1[jx][2],
                                                       c0[jx][3] + c1[jx][3]));
                }
            } else {   // cols 48..55: col 50 is the constant-1.0 bias feed
                const int col0 = 48 + 2 * t4;
#pragma unroll
                for (int jx = 0; jx < 2; jx++) {
                    float v0 = (col0 == 50) ? 1.f : fmaxf(c0[jx][0] + c1[jx][0], 0.f);
                    float v1 = fmaxf(c0[jx][1] + c1[jx][1], 0.f);   // odd col, never 50
                    float v2 = (col0 == 50) ? 1.f : fmaxf(c0[jx][2] + c1[jx][2], 0.f);
                    float v3 = fmaxf(c0[jx][3] + c1[jx][3], 0.f);
                    A3h[jx][3][0] = pack2(v0, v1);
                    A3h[jx][3][1] = pack2(v2, v3);
                }
            }
        }

        // ---- layer 3: z3 = H2 @ W2d (+b2 via col-50 feed), relu, accum ----
#pragma unroll
        for (int nt = 0; nt < 7; nt++) {
            float c0[2][4] = {{0.f,0.f,0.f,0.f},{0.f,0.f,0.f,0.f}};
            float c1[2][4] = {{0.f,0.f,0.f,0.f},{0.f,0.f,0.f,0.f}};
            const int ro = (nt * 8 + g) * WST + t4 * 4;
#pragma unroll
            for (int kt = 0; kt < 3; kt++) {
                uint2 bb = *(const uint2*)(W2 + ro + kt * 16);
                mma16816((kt < 2) ? c0[0] : c1[0], A3h[0][kt], bb.x, bb.y);
                mma16816((kt < 2) ? c0[1] : c1[1], A3h[1][kt], bb.x, bb.y);
            }
            {
                uint32_t b0 = *(const uint32_t*)(W2 + ro + 48);
                mma16808(c1[0], A3h[0][3][0], A3h[0][3][1], b0);
                mma16808(c1[1], A3h[1][3][0], A3h[1][3][1], b0);
            }
#pragma unroll
            for (int jx = 0; jx < 2; jx++) {
                Fr[nt * 4 + 0] += fmaxf(c0[jx][0] + c1[jx][0], 0.f);
                Fr[nt * 4 + 1] += fmaxf(c0[jx][1] + c1[jx][1], 0.f);
                Fr[nt * 4 + 2] += fmaxf(c0[jx][2] + c1[jx][2], 0.f);
                Fr[nt * 4 + 3] += fmaxf(c0[jx][3] + c1[jx][3], 0.f);
            }
        }
    }

    // ---- packed-half2 partial writeback (W3 folded post-sum in finalize) ----
    // thread owns column pairs (col0, col0+1), col0 = nt*8 + 2*t4 (even).
    const int i0 = ib * 128 + w * 16 + g;
    const long base = (long)(m * 16 + jc) * NOBJ;
#pragma unroll
    for (int nt = 0; nt < 7; nt++) {
        const int col0 = nt * 8 + 2 * t4;
        if (col0 < 50) {   // col0 even; col0+1 <= 49 whenever col0 < 50
            g_partial[(base + i0) * 25 + (col0 >> 1)] =
                pack2(Fr[nt * 4 + 0], Fr[nt * 4 + 1]);
            g_partial[(base + i0 + 8) * 25 + (col0 >> 1)] =
                pack2(Fr[nt * 4 + 2], Fr[nt * 4 + 3]);
        }
    }
}

// warp-per-(c,i) finalize: jc-reduce (fp32) of packed partials, fold W3, head MLP
__global__ void __launch_bounds__(256)
finalize_kernel(const float* __restrict__ gW3, const float* __restrict__ gb3,
                const float* __restrict__ aW0, const float* __restrict__ ab0,
                const float* __restrict__ aW1, const float* __restrict__ ab1,
                float* __restrict__ out)
{
    const int warp = blockIdx.x * (blockDim.x >> 5) + (threadIdx.x >> 5);
    const int lane = threadIdx.x & 31;

    if (warp >= 2048) return;
    const int c = warp >> 10;
    const int i = warp & 1023;

    float F[20];
#pragma unroll
    for (int o = 0; o < 20; o++) F[o] = 0.f;

    // 4 actor classes x 25 column-pairs = 100 work items
    for (int idx = lane; idx < 100; idx += 32) {
        const int a = idx / 25, pr = idx % 25;
        const int mm = a * 2 + c;
        const uint32_t* gp = g_partial + ((long)(mm * 16) * NOBJ + i) * 25 + pr;
        float s0 = 0.f, s1 = 0.f;
#pragma unroll
        for (int jcc = 0; jcc < 16; jcc++) {
            uint32_t pkd = gp[(long)jcc * NOBJ * 25];
            half2 h = *reinterpret_cast<half2*>(&pkd);
            float2 f = __half22float2(h);
            s0 += f.x;  s1 += f.y;
        }
        const float* w3a = gW3 + mm * 1000 + (2 * pr) * 20;
        const float* w3b = w3a + 20;
#pragma unroll
        for (int o = 0; o < 20; o++)
            F[o] = fmaf(s1, w3b[o], fmaf(s0, w3a[o], F[o]));
    }
#pragma unroll
    for (int off = 16; off; off >>= 1)
#pragma unroll
        for (int o = 0; o < 20; o++)
            F[o] += __shfl_xor_sync(0xffffffffu, F[o], off);
#pragma unroll
    for (int o = 0; o < 20; o++) {
        float b = gb3[(0 + c) * 20 + o] + gb3[(2 + c) * 20 + o]
                + gb3[(4 + c) * 20 + o] + gb3[(6 + c) * 20 + o];
        F[o] += 1024.f * b;
    }

    float p = 0.f;
    for (int l = lane; l < 50; l += 32) {
        float h = ab0[c * 50 + l];
#pragma unroll
        for (int o = 0; o < 20; o++)
            h = fmaf(F[o], aW0[c * 1000 + o * 50 + l], h);
        p = fmaf(fmaxf(h, 0.f), aW1[c * 50 + l], p);
    }
#pragma unroll
    for (int off = 16; off; off >>= 1)
        p += __shfl_xor_sync(0xffffffffu, p, off);
    if (lane == 0) out[c * 1024 + i] = p + ab1[c];
}

extern "C" void kernel_launch(void* const* d_in, const int* in_sizes, int n_in,
                              void* d_out, int out_size)
{
    const float* obj0  = (const float*)d_in[0];
    const float* obj1  = (const float*)d_in[1];
    const float* prev0 = (const float*)d_in[2];
    const float* prev1 = (const float*)d_in[3];
    const float* gW0   = (const float*)d_in[4];
    const float* gb0   = (const float*)d_in[5];
    const float* gW1   = (const float*)d_in[6];
    const float* gb1   = (const float*)d_in[7];
    const float* gW2   = (const float*)d_in[8];
    const float* gb2   = (const float*)d_in[9];
    const float* gW3   = (const float*)d_in[10];
    const float* gb3   = (const float*)d_in[11];
    const float* aW0   = (const float*)d_in[12];
    const float* ab0   = (const float*)d_in[13];
    const float* aW1   = (const float*)d_in[14];
    const float* ab1   = (const float*)d_in[15];

    dim3 grid(8, 8, 16);   // (module, i-block, j-chunk of 64) -> 1024 CTAs
    pair_kernel<<<grid, TPB>>>(obj0, obj1, prev0, prev1,
                               gW0, gb0, gW1, gb1, gW2, gb2);
    finalize_kernel<<<256, 256>>>(gW3, gb3, aW0, ab0, aW1, ab1, (float*)d_out);
}

// round 17
// speedup vs baseline: 1.0545x; 1.0066x over previous
#include <cuda_runtime.h>
#include <cuda_fp16.h>
#include <cstdint>

#define NOBJ 1024
#define TPB  256
#define JB   64        // actors per CTA chunk (16 chunks -> 1024 CTAs, 7 waves)
#define WST  80        // SMEM weight row stride (halfs): 160B == 32 mod 128
                       // -> conflict-free ld.shared.v2.u32 of B fragments

// partial[m][jc][i][25] as packed half2 pairs (cols 2p, 2p+1).
// Fully overwritten every launch by the 1024 CTAs.
__device__ uint32_t g_partial[8 * 16 * NOBJ * 25];

// ---------------------------------------------------------------------------
// mma.m16n8k16 row.col f32.f16.f16.f32
// A frag (4 b32): a0=(row g, k=2t4,2t4+1) a1=(g+8, same) a2=(g, +8) a3=(g+8, +8)
// B frag (2 b32): b0=(k=2t4,2t4+1, n=g)   b1=(k=+8, n=g)
// C frag (4 f32): c0=(g, n=2t4) c1=(g, 2t4+1) c2=(g+8, 2t4) c3=(g+8, 2t4+1)
// ---------------------------------------------------------------------------
__device__ __forceinline__ void mma16816(float c[4], const uint32_t a[4],
                                         uint32_t b0, uint32_t b1)
{
    asm("mma.sync.aligned.m16n8k16.row.col.f32.f16.f16.f32 "
        "{%0,%1,%2,%3}, {%4,%5,%6,%7}, {%8,%9}, {%0,%1,%2,%3};\n"
        : "+f"(c[0]), "+f"(c[1]), "+f"(c[2]), "+f"(c[3])
        : "r"(a[0]), "r"(a[1]), "r"(a[2]), "r"(a[3]), "r"(b0), "r"(b1));
}

// m16n8k8: A frag 2 regs (a0=(row g, k=2t4,2t4+1), a1=(g+8, same)), B frag 1 reg
__device__ __forceinline__ void mma16808(float c[4], uint32_t a0, uint32_t a1,
                                         uint32_t b0)
{
    asm("mma.sync.aligned.m16n8k8.row.col.f32.f16.f16.f32 "
        "{%0,%1,%2,%3}, {%4,%5}, {%6}, {%0,%1,%2,%3};\n"
        : "+f"(c[0]), "+f"(c[1]), "+f"(c[2]), "+f"(c[3])
        : "r"(a0), "r"(a1), "r"(b0));
}

__device__ __forceinline__ uint32_t pack2(float x, float y)
{
    half2 h = __floats2half2_rn(x, y);
    return *reinterpret_cast<uint32_t*>(&h);
}

// relu on a packed half2 word: rn is monotone and rn(0)=0, so
// rn(max(v,0)) == max(rn(v),0) -- numerically identical to fp32 relu-then-pack.
__device__ __forceinline__ uint32_t relu2(uint32_t x)
{
    half2 h = *reinterpret_cast<half2*>(&x);
    half2 r = __hmax2(h, __floats2half2_rn(0.f, 0.f));
    return *reinterpret_cast<uint32_t*>(&r);
}

// dithered pair: w_e = rn(w); w_o = rn(2w - w_e)  (error of w_o ~ -error(w_e))
__device__ __forceinline__ void dither_w(float v, half& we, half& wo)
{
    we = __float2half_rn(v);
    wo = __float2half_rn(2.f * v - __half2float(we));
}

// k-interleaved SMEM slot for weight element at contraction index k (0..63):
// fragment thread t4 reads halfs {2t4, 2t4+1, 2t4+8, 2t4+9} of each 16-wide
// kt tile; store them contiguously so one v2 load fetches both b32 words.
__device__ __forceinline__ int kslot(int k)
{
    int kt = k >> 4, kk = k & 15;
    int t4s = (kk < 8) ? (kk >> 1) : ((kk - 8) >> 1);
    int c   = (kk < 8) ? (kk & 1)  : (2 + (kk & 1));
    return kt * 16 + t4s * 4 + c;
}

__global__ void __launch_bounds__(TPB, 1)
pair_kernel(const float* __restrict__ obj0, const float* __restrict__ obj1,
            const float* __restrict__ prev0, const float* __restrict__ prev1,
            const float* __restrict__ gW0, const float* __restrict__ gb0,
            const float* __restrict__ gW1, const float* __restrict__ gb1,
            const float* __restrict__ gW2, const float* __restrict__ gb2)
{
    const int m  = blockIdx.x;   // module (actor class = m>>1, actee class = m&1)
    const int ib = blockIdx.y;   // i-block (128 actees)
    const int jc = blockIdx.z;   // j-chunk (64 actors, 16 chunks)
    const int t  = threadIdx.x;
    const int w  = t >> 5;
    const int lane = t & 31;
    const int t4 = lane & 3;
    const int g  = lane >> 2;

    const int ac = m >> 1;
    const float* actor = (ac == 0) ? obj0 : (ac == 1) ? obj1 : (ac == 2) ? prev0 : prev1;
    const float* actee = (m & 1) ? obj1 : obj0;

    // Interleaved transposed weights; row k=50 carries the bias (fed by the
    // constant-1.0 col-50 of H). Even/odd dithered copies selected by PAIR
    // parity so a j-pair shares its B loads.
    __shared__ alignas(16) half Wt1e[64 * WST], Wt1o[64 * WST];
    __shared__ alignas(16) half Wt2e[64 * WST], Wt2o[64 * WST];
    __shared__ float alph[JB];

    for (int x = t; x < 64 * WST; x += TPB) {
        Wt1e[x] = __float2half(0.f);  Wt1o[x] = __float2half(0.f);
        Wt2e[x] = __float2half(0.f);  Wt2o[x] = __float2half(0.f);
    }
    __syncthreads();
    for (int x = t; x < 51 * 50; x += TPB) {
        int k = x / 50, n = x % 50;
        int s = n * WST + kslot(k);
        float w1 = (k < 50) ? gW1[m * 2500 + k * 50 + n] : gb1[m * 50 + n];
        float w2 = (k < 50) ? gW2[m * 2500 + k * 50 + n] : gb2[m * 50 + n];
        half we, wo;
        dither_w(w1, we, wo);  Wt1e[s] = we;  Wt1o[s] = wo;
        dither_w(w2, we, wo);  Wt2e[s] = we;  Wt2o[s] = wo;
    }
    if (t < JB) alph[t] = actor[jc * JB + t];

    // per-thread layer-1 constants at this thread's 16 fragment columns
    // (kt=3 upper slots k=56..63 are never used: m16n8k8 covers only 48..55)
    float pc[16], qc[16], rc[16];
#pragma unroll
    for (int kt = 0; kt < 4; kt++)
#pragma unroll
        for (int s = 0; s < 4; s++) {
            int col = kt * 16 + 2 * t4 + ((s >> 1) << 3) + (s & 1);
            int idx = kt * 4 + s;
            pc[idx] = (col < 50) ? gW0[m * 100 + col] : 0.f;        // W0[m][0][col]
            qc[idx] = (col < 50) ? gW0[m * 100 + 50 + col] : 0.f;   // W0[m][1][col]
            rc[idx] = (col < 50) ? gb0[m * 50 + col]
                                 : (col == 50 ? 1.f : 0.f);          // bias-feed col
        }
    const float betaA = actee[ib * 128 + w * 16 + g];
    const float betaB = actee[ib * 128 + w * 16 + g + 8];

    float Fr[28];
#pragma unroll
    for (int x = 0; x < 28; x++) Fr[x] = 0.f;

    uint32_t A3h[2][4][4];   // [·][3][2..3] unused (k 56..63 handled by k8 MMA)

    __syncthreads();    // the ONLY barrier before the writeback

    for (int jj = 0; jj < JB; jj += 2) {
        // pair-parity dithered weight set (both j's of the pair share B loads)
        const int par = (jj >> 1) & 1;
        const half* __restrict__ W1 = par ? Wt1o : Wt1e;
        const half* __restrict__ W2 = par ? Wt2o : Wt2e;

        // ---- layer 1 (rank-1 collapse) -> A fragments for both j's ----
        // kt=3: only the low k-half (48..55) is needed (k8 MMA).
        uint32_t A2h[2][4][4];
#pragma unroll
        for (int jx = 0; jx < 2; jx++) {
            const float al = alph[jj + jx];
#pragma unroll
            for (int kt = 0; kt < 4; kt++) {
                const int b = kt * 4;
                float u0 = fmaf(al, pc[b + 0], rc[b + 0]);
                float u1 = fmaf(al, pc[b + 1], rc[b + 1]);
                A2h[jx][kt][0] = relu2(pack2(fmaf(betaA, qc[b + 0], u0),
                                             fmaf(betaA, qc[b + 1], u1)));
                A2h[jx][kt][1] = relu2(pack2(fmaf(betaB, qc[b + 0], u0),
                                             fmaf(betaB, qc[b + 1], u1)));
                if (kt < 3) {
                    float u2 = fmaf(al, pc[b + 2], rc[b + 2]);
                    float u3 = fmaf(al, pc[b + 3], rc[b + 3]);
                    A2h[jx][kt][2] = relu2(pack2(fmaf(betaA, qc[b + 2], u2),
                                                 fmaf(betaA, qc[b + 3], u3)));
                    A2h[jx][kt][3] = relu2(pack2(fmaf(betaB, qc[b + 2], u2),
                                                 fmaf(betaB, qc[b + 3], u3)));
                }
            }
        }

        // ---- layer 2: z2 = H1 @ W1d (+b1 via col-50 feed) -> A3 (both j) ----
        // nt = 0..6 (cols 56..63 all-zero). kt 0..2: k16; kt 3: k8 (k 48..55).
#pragma unroll
        for (int nt = 0; nt < 7; nt++) {
            float c0[2][4] = {{0.f,0.f,0.f,0.f},{0.f,0.f,0.f,0.f}};
            float c1[2][4] = {{0.f,0.f,0.f,0.f},{0.f,0.f,0.f,0.f}};
            const int ro = (nt * 8 + g) * WST + t4 * 4;
#pragma unroll
            for (int kt = 0; kt < 3; kt++) {
                uint2 bb = *(const uint2*)(W1 + ro + kt * 16);
                mma16816((kt < 2) ? c0[0] : c1[0], A2h[0][kt], bb.x, bb.y);
                mma16816((kt < 2) ? c0[1] : c1[1], A2h[1][kt], bb.x, bb.y);
            }
            {
                uint32_t b0 = *(const uint32_t*)(W1 + ro + 48);
                mma16808(c1[0], A2h[0][3][0], A2h[0][3][1], b0);
                mma16808(c1[1], A2h[1][3][0], A2h[1][3][1], b0);
            }
            const int kt2 = nt >> 1, s0 = (nt & 1) ? 2 : 0;
            if (nt != 6) {
#pragma unroll
                for (int jx = 0; jx < 2; jx++) {
                    A3h[jx][kt2][s0]     = relu2(pack2(c0[jx][0] + c1[jx][0],
                                                       c0[jx][1] + c1[jx][1]));
                    A3h[jx][kt2][s0 + 1] = relu2(pack2(c0[jx][2] + c1[jx][2],
                                                       c0[jx][3] + c1[jx][3]));
                }
            } else {   // cols 48..55: col 50 is the constant-1.0 bias feed
                const int col0 = 48 + 2 * t4;
#pragma unroll
                for (int jx = 0; jx < 2; jx++) {
                    float v0 = (col0 == 50) ? 1.f : fmaxf(c0[jx][0] + c1[jx][0], 0.f);
                    float v1 = fmaxf(c0[jx][1] + c1[jx][1], 0.f);   // odd col, never 50
                    float v2 = (col0 == 50) ? 1.f : fmaxf(c0[jx][2] + c1[jx][2], 0.f);
                    float v3 = fmaxf(c0[jx][3] + c1[jx][3], 0.f);
                    A3h[jx][3][0] = pack2(v0, v1);
                    A3h[jx][3][1] = pack2(v2, v3);
                }
            }
        }

        // ---- layer 3: z3 = H2 @ W2d (+b2 via col-50 feed), relu, accum ----
#pragma unroll
        for (int nt = 0; nt < 7; nt++) {
            float c0[2][4] = {{0.f,0.f,0.f,0.f},{0.f,0.f,0.f,0.f}};
            float c1[2][4] = {{0.f,0.f,0.f,0.f},{0.f,0.f,0.f,0.f}};
            const int ro = (nt * 8 + g) * WST + t4 * 4;
#pragma unroll
            for (int kt = 0; kt < 3; kt++) {
                uint2 bb = *(const uint2*)(W2 + ro + kt * 16);
                mma16816((kt < 2) ? c0[0] : c1[0], A3h[0][kt], bb.x, bb.y);
                mma16816((kt < 2) ? c0[1] : c1[1], A3h[1][kt], bb.x, bb.y);
            }
            {
                uint32_t b0 = *(const uint32_t*)(W2 + ro + 48);
                mma16808(c1[0], A3h[0][3][0], A3h[0][3][1], b0);
                mma16808(c1[1], A3h[1][3][0], A3h[1][3][1], b0);
            }
#pragma unroll
            for (int jx = 0; jx < 2; jx++) {
                Fr[nt * 4 + 0] += fmaxf(c0[jx][0] + c1[jx][0], 0.f);
                Fr[nt * 4 + 1] += fmaxf(c0[jx][1] + c1[jx][1], 0.f);
                Fr[nt * 4 + 2] += fmaxf(c0[jx][2] + c1[jx][2], 0.f);
                Fr[nt * 4 + 3] += fmaxf(c0[jx][3] + c1[jx][3], 0.f);
            }
        }
    }

    // ---- packed-half2 partial writeback (W3 folded post-sum in finalize) ----
    // thread owns column pairs (col0, col0+1), col0 = nt*8 + 2*t4 (even).
    const int i0 = ib * 128 + w * 16 + g;
    const long base = (long)(m * 16 + jc) * NOBJ;
#pragma unroll
    for (int nt = 0; nt < 7; nt++) {
        const int col0 = nt * 8 + 2 * t4;
        if (col0 < 50) {   // col0 even; col0+1 <= 49 whenever col0 < 50
            g_partial[(base + i0) * 25 + (col0 >> 1)] =
                pack2(Fr[nt * 4 + 0], Fr[nt * 4 + 1]);
            g_partial[(base + i0 + 8) * 25 + (col0 >> 1)] =
                pack2(Fr[nt * 4 + 2], Fr[nt * 4 + 3]);
        }
    }
}

// finalize: one block (4 warps) per (c,i). Warp a reduces actor class a
// (25 column-pairs x 16 jc chunks, fp32), classes combined via SMEM, then
// warp 0 applies the head MLP. 8192 warps total -> 4x the latency hiding.
__global__ void __launch_bounds__(128)
finalize_kernel(const float* __restrict__ gW3, const float* __restrict__ gb3,
                const float* __restrict__ aW0, const float* __restrict__ ab0,
                const float* __restrict__ aW1, const float* __restrict__ ab1,
                float* __restrict__ out)
{
    const int bid  = blockIdx.x;        // 0..2047
    const int c    = bid >> 10;
    const int i    = bid & 1023;
    const int a    = threadIdx.x >> 5;  // actor class handled by this warp
    const int lane = threadIdx.x & 31;

    __shared__ float Fs[4][20];
    __shared__ float Fc[20];

    const int mm = a * 2 + c;
    float F[20];
#pragma unroll
    for (int o = 0; o < 20; o++) F[o] = 0.f;

    if (lane < 25) {
        const int pr = lane;
        const uint32_t* gp = g_partial + ((long)(mm * 16) * NOBJ + i) * 25 + pr;
        float s0 = 0.f, s1 = 0.f;
#pragma unroll
        for (int jcc = 0; jcc < 16; jcc++) {
            uint32_t pkd = gp[(long)jcc * NOBJ * 25];
            half2 h = *reinterpret_cast<half2*>(&pkd);
            float2 f = __half22float2(h);
            s0 += f.x;  s1 += f.y;
        }
        const float* w3a = gW3 + mm * 1000 + (2 * pr) * 20;
        const float* w3b = w3a + 20;
#pragma unroll
        for (int o = 0; o < 20; o++)
            F[o] = fmaf(s1, w3b[o], fmaf(s0, w3a[o], F[o]));
    }
#pragma unroll
    for (int off = 16; off; off >>= 1)
#pragma unroll
        for (int o = 0; o < 20; o++)
            F[o] += __shfl_xor_sync(0xffffffffu, F[o], off);
    if (lane < 20) Fs[a][lane] = F[lane];
    __syncthreads();

    // combine the 4 actor classes + the 1024 * sum(gb3) bias term
    if (threadIdx.x < 20) {
        const int o = threadIdx.x;
        float b = gb3[(0 + c) * 20 + o] + gb3[(2 + c) * 20 + o]
                + gb3[(4 + c) * 20 + o] + gb3[(6 + c) * 20 + o];
        Fc[o] = Fs[0][o] + Fs[1][o] + Fs[2][o] + Fs[3][o] + 1024.f * b;
    }
    __syncthreads();

    // head MLP: 20 -> 50 (relu) -> 1, warp 0 only
    if (a == 0) {
        float Fh[20];
#pragma unroll
        for (int o = 0; o < 20; o++) Fh[o] = Fc[o];

        float p = 0.f;
        for (int l = lane; l < 50; l += 32) {
            float h = ab0[c * 50 + l];
#pragma unroll
            for (int o = 0; o < 20; o++)
                h = fmaf(Fh[o], aW0[c * 1000 + o * 50 + l], h);
            p = fmaf(fmaxf(h, 0.f), aW1[c * 50 + l], p);
        }
#pragma unroll
        for (int off = 16; off; off >>= 1)
            p += __shfl_xor_sync(0xffffffffu, p, off);
        if (lane == 0) out[c * 1024 + i] = p + ab1[c];
    }
}

extern "C" void kernel_launch(void* const* d_in, const int* in_sizes, int n_in,
                              void* d_out, int out_size)
{
    const float* obj0  = (const float*)d_in[0];
    const float* obj1  = (const float*)d_in[1];
    const float* prev0 = (const float*)d_in[2];
    const float* prev1 = (const float*)d_in[3];
    const float* gW0   = (const float*)d_in[4];
    const float* gb0   = (const float*)d_in[5];
    const float* gW1   = (const float*)d_in[6];
    const float* gb1   = (const float*)d_in[7];
    const float* gW2   = (const float*)d_in[8];
    const float* gb2   = (const float*)d_in[9];
    const float* gW3   = (const float*)d_in[10];
    const float* gb3   = (const float*)d_in[11];
    const float* aW0   = (const float*)d_in[12];
    const float* ab0   = (const float*)d_in[13];
    const float* aW1   = (const float*)d_in[14];
    const float* ab1   = (const float*)d_in[15];

    dim3 grid(8, 8, 16);   // (module, i-block, j-chunk of 64) -> 1024 CTAs
    pair_kernel<<<grid, TPB>>>(obj0, obj1, prev0, prev1,
                               gW0, gb0, gW1, gb1, gW2, gb2);
    finalize_kernel<<<2048, 128>>>(gW3, gb3, aW0, ab0, aW1, ab1, (float*)d_out);
}